// round 16
// baseline (speedup 1.0000x reference)
#include <cuda_runtime.h>
#include <cuda_fp16.h>
#include <math.h>
#include <stdint.h>

// Problem constants
#define Bn   256
#define In   256
#define Hn   512
#define An   400
#define Vn   50000
#define OOVn 50
#define Pn   (Vn + OOVn)      // 50050
#define H2   (2 * Hn)          // 1024
#define DIN  (An + Hn)         // 912 = 57*16
#define NBN  391               // fc2 n-blocks (391*128 = 50048)
#define VP   (NBN * 128)       // 50048 padded rows

// Scratch (static device globals: allocation-free rule)
__device__ float g_h[Bn * Hn];
__device__ float g_e[Bn * An];
__device__ float g_att[Bn * An];
__device__ float g_ctxp[4 * Bn * An];
__device__ float g_ctx[Bn * An];
__device__ float g_din[Bn * DIN];
__device__ __half g_fc1h[Bn * H2];               // fc1 out, fp16 (fc2 A operand)
__device__ __half g_wh[(size_t)VP * H2];         // fc2_w fp16 padded, 102.5 MB
__device__ float g_gen[Bn];
__device__ float g_sum[Bn];
__device__ float g_exp[(size_t)Bn * Vn];         // 51.2 MB

__device__ __forceinline__ float sigmoidf(float x) { return 1.0f / (1.0f + expf(-x)); }

__device__ __forceinline__ float warp_sum(float v) {
    #pragma unroll
    for (int o = 16; o; o >>= 1) v += __shfl_xor_sync(0xFFFFFFFFu, v, o);
    return v;
}

__device__ __forceinline__ float block_sum(float v, float* red) {
    int lane = threadIdx.x & 31, warp = threadIdx.x >> 5;
    v = warp_sum(v);
    if (lane == 0) red[warp] = v;
    __syncthreads();
    int nw = (blockDim.x + 31) >> 5;
    float r = (threadIdx.x < nw) ? red[threadIdx.x] : 0.0f;
    if (warp == 0) r = warp_sum(r);
    if (threadIdx.x == 0) red[0] = r;
    __syncthreads();
    return red[0];
}

__device__ __forceinline__ float block_max(float v, float* red) {
    int lane = threadIdx.x & 31, warp = threadIdx.x >> 5;
    #pragma unroll
    for (int o = 16; o; o >>= 1) v = fmaxf(v, __shfl_xor_sync(0xFFFFFFFFu, v, o));
    if (lane == 0) red[warp] = v;
    __syncthreads();
    int nw = (blockDim.x + 31) >> 5;
    float r = (threadIdx.x < nw) ? red[threadIdx.x] : -INFINITY;
    if (warp == 0) {
        #pragma unroll
        for (int o = 16; o; o >>= 1) r = fmaxf(r, __shfl_xor_sync(0xFFFFFFFFu, r, o));
    }
    if (threadIdx.x == 0) red[0] = r;
    __syncthreads();
    return red[0];
}

// ---------------------------------------------------------------------------
// K0: fc2_w (fp32 [50000][1024]) -> g_wh (fp16 [50048][1024], pad rows = 0)
// ---------------------------------------------------------------------------
__global__ void k_cvt2(const float* __restrict__ w) {
    size_t u = (size_t)blockIdx.x * blockDim.x + threadIdx.x;   // float4 index
    size_t row = u >> 8;
    int pos = (int)(u & 255) * 4;
    if (row >= VP) return;
    float4 v = make_float4(0.f, 0.f, 0.f, 0.f);
    if (row < Vn) v = *(const float4*)(w + row * H2 + pos);
    __half2 p0 = __floats2half2_rn(v.x, v.y);
    __half2 p1 = __floats2half2_rn(v.z, v.w);
    uint2 o;
    o.x = *(unsigned*)&p0;
    o.y = *(unsigned*)&p1;
    *(uint2*)(g_wh + row * H2 + pos) = o;
}

// ---------------------------------------------------------------------------
// K1: LSTM cell — proven R11 version (grid 8x32)
// ---------------------------------------------------------------------------
__global__ __launch_bounds__(256) void k_lstm(const float* __restrict__ x,
                                              const float* __restrict__ W_ih,
                                              const float* __restrict__ b_ih,
                                              const float* __restrict__ b_hh) {
    int jc = blockIdx.x;
    int b0 = blockIdx.y * 8;
    __shared__ float sx[8][In];
    for (int idx = threadIdx.x; idx < 8 * In; idx += blockDim.x) {
        int bb = idx >> 8, k = idx & 255;
        sx[bb][k] = x[(b0 + bb) * In + k];
    }
    __syncthreads();
    int warp = threadIdx.x >> 5, lane = threadIdx.x & 31;
    for (int jj = 0; jj < 8; jj++) {
        int j = jc * 64 + jj * 8 + warp;
        const float* wi = W_ih + (size_t)j * In;
        const float* wg = W_ih + (size_t)(2 * Hn + j) * In;
        const float* wo = W_ih + (size_t)(3 * Hn + j) * In;
        float wiR[8], wgR[8], woR[8];
        #pragma unroll
        for (int p = 0; p < 8; p++) {
            int k = lane + 32 * p;
            wiR[p] = wi[k]; wgR[p] = wg[k]; woR[p] = wo[k];
        }
        float bi = b_ih[j] + b_hh[j];
        float bg = b_ih[2 * Hn + j] + b_hh[2 * Hn + j];
        float bo = b_ih[3 * Hn + j] + b_hh[3 * Hn + j];
        #pragma unroll
        for (int bb = 0; bb < 8; bb++) {
            float ai = 0.f, ag = 0.f, ao = 0.f;
            #pragma unroll
            for (int p = 0; p < 8; p++) {
                float xv = sx[bb][lane + 32 * p];
                ai = fmaf(xv, wiR[p], ai);
                ag = fmaf(xv, wgR[p], ag);
                ao = fmaf(xv, woR[p], ao);
            }
            ai = warp_sum(ai); ag = warp_sum(ag); ao = warp_sum(ao);
            if (lane == 0) {
                float ai2 = ai + bi, ag2 = ag + bg, ao2 = ao + bo;
                float c = sigmoidf(ai2) * tanhf(ag2);
                g_h[(b0 + bb) * Hn + j] = sigmoidf(ao2) * tanhf(c);
            }
        }
    }
}

// ---------------------------------------------------------------------------
// K2a/K2b: attention (proven R11)
// ---------------------------------------------------------------------------
__global__ __launch_bounds__(256) void k_attn_e(const float* __restrict__ enc_state,
                                                const float* __restrict__ Wh_w,
                                                const float* __restrict__ Wh_b,
                                                const float* __restrict__ Ws_w,
                                                const float* __restrict__ Ws_b) {
    int ac = blockIdx.x;
    int b0 = blockIdx.y * 8;
    __shared__ float ss[8][Hn];
    __shared__ float sh[8][Hn];
    for (int idx = threadIdx.x; idx < 8 * Hn; idx += blockDim.x) {
        int bb = idx >> 9, k = idx & 511;
        ss[bb][k] = enc_state[(b0 + bb) * Hn + k];
        sh[bb][k] = g_h[(b0 + bb) * Hn + k];
    }
    __syncthreads();
    int warp = threadIdx.x >> 5, lane = threadIdx.x & 31;
    for (int aa = warp; aa < 50; aa += 8) {
        int a = ac * 50 + aa;
        const float* w1 = Wh_w + (size_t)a * Hn;
        const float* w2 = Ws_w + (size_t)a * Hn;
        float w1R[16], w2R[16];
        #pragma unroll
        for (int p = 0; p < 16; p++) {
            int k = lane + 32 * p;
            w1R[p] = w1[k]; w2R[p] = w2[k];
        }
        float bias = Wh_b[a] + Ws_b[a];
        #pragma unroll
        for (int bb = 0; bb < 8; bb++) {
            float acc = 0.f;
            #pragma unroll
            for (int p = 0; p < 16; p++) {
                int k = lane + 32 * p;
                acc = fmaf(ss[bb][k], w1R[p], fmaf(sh[bb][k], w2R[p], acc));
            }
            acc = warp_sum(acc);
            if (lane == 0) g_e[(b0 + bb) * An + a] = tanhf(acc + bias);
        }
    }
}

__global__ __launch_bounds__(256) void k_attn_soft(const float* __restrict__ vvec) {
    int b = blockIdx.x;
    __shared__ float red[32];
    float m = -INFINITY;
    for (int i = threadIdx.x; i < An; i += blockDim.x) m = fmaxf(m, g_e[b * An + i]);
    m = block_max(m, red);
    float s = 0.f;
    for (int i = threadIdx.x; i < An; i += blockDim.x) s += expf(g_e[b * An + i] - m);
    s = block_sum(s, red);
    float inv = 1.0f / s;
    for (int i = threadIdx.x; i < An; i += blockDim.x)
        g_att[b * An + i] = vvec[i] * expf(g_e[b * An + i] - m) * inv;
}

// ---------------------------------------------------------------------------
// K3: context partials (proven)
// ---------------------------------------------------------------------------
__global__ void k_ctx(const float* __restrict__ enc_out) {
    int slice = blockIdx.x;
    int b = blockIdx.y;
    int a0 = slice * 100;
    __shared__ float sa[100];
    if (threadIdx.x < 100) sa[threadIdx.x] = g_att[b * An + a0 + threadIdx.x];
    __syncthreads();
    int e = threadIdx.x;
    if (e < An) {
        const float* base = enc_out + ((size_t)b * An + a0) * An + e;
        float acc = 0.f;
        #pragma unroll 5
        for (int i = 0; i < 100; i++) acc = fmaf(sa[i], base[(size_t)i * An], acc);
        g_ctxp[((size_t)slice * Bn + b) * An + e] = acc;
    }
}

__global__ void k_ctxred() {
    int b = blockIdx.x;
    int e = threadIdx.x;
    if (e < An) {
        float s = g_ctxp[((size_t)0 * Bn + b) * An + e]
                + g_ctxp[((size_t)1 * Bn + b) * An + e]
                + g_ctxp[((size_t)2 * Bn + b) * An + e]
                + g_ctxp[((size_t)3 * Bn + b) * An + e];
        g_ctx[b * An + e] = s;
    }
}

// ---------------------------------------------------------------------------
// K5: gen gate + dec_in + g_sum zero (proven R11)
// ---------------------------------------------------------------------------
__global__ void k_gendin(const float* __restrict__ x, const float* __restrict__ pg1,
                         const float* __restrict__ pg2, const float* __restrict__ pg3) {
    int b = blockIdx.x;
    __shared__ float red[32];
    float acc = 0.f;
    for (int k = threadIdx.x; k < In; k += blockDim.x) acc = fmaf(x[b * In + k], pg1[k], acc);
    for (int k = threadIdx.x; k < An; k += blockDim.x) acc = fmaf(g_ctx[b * An + k], pg2[k], acc);
    for (int k = threadIdx.x; k < Hn; k += blockDim.x) acc = fmaf(g_h[b * Hn + k], pg3[k], acc);
    acc = block_sum(acc, red);
    if (threadIdx.x == 0) {
        g_gen[b] = sigmoidf(acc);
        g_sum[b] = 0.0f;
    }
    for (int i = threadIdx.x; i < DIN; i += blockDim.x) {
        float v = (i < An) ? g_ctx[b * An + i] : g_h[b * Hn + (i - An)];
        g_din[b * DIN + i] = v;
    }
}

// ---------------------------------------------------------------------------
// GEMM machinery
// ---------------------------------------------------------------------------
#define CP_ASYNC(dst, src)        asm volatile("cp.async.cg.shared.global [%0], [%1], 16;" :: "r"(dst), "l"(src))
#define CP_COMMIT()               asm volatile("cp.async.commit_group;")
#define CP_WAIT(n)                asm volatile("cp.async.wait_group %0;" :: "n"(n))

__device__ __forceinline__ void mma_tf32(float c[4], const unsigned a[4], const unsigned b[2]) {
    asm volatile(
        "mma.sync.aligned.m16n8k8.row.col.f32.tf32.tf32.f32 "
        "{%0,%1,%2,%3}, {%4,%5,%6,%7}, {%8,%9}, {%0,%1,%2,%3};"
        : "+f"(c[0]), "+f"(c[1]), "+f"(c[2]), "+f"(c[3])
        : "r"(a[0]), "r"(a[1]), "r"(a[2]), "r"(a[3]), "r"(b[0]), "r"(b[1]));
}

__device__ __forceinline__ void mma_f16(float c[4], const unsigned a[4], const unsigned b[2]) {
    asm volatile(
        "mma.sync.aligned.m16n8k16.row.col.f32.f16.f16.f32 "
        "{%0,%1,%2,%3}, {%4,%5,%6,%7}, {%8,%9}, {%0,%1,%2,%3};"
        : "+f"(c[0]), "+f"(c[1]), "+f"(c[2]), "+f"(c[3])
        : "r"(a[0]), "r"(a[1]), "r"(a[2]), "r"(a[3]), "r"(b[0]), "r"(b[1]));
}

__device__ __forceinline__ void ldsm_x4(unsigned& r0, unsigned& r1, unsigned& r2, unsigned& r3,
                                        unsigned addr) {
    asm volatile("ldmatrix.sync.aligned.m8n8.x4.shared.b16 {%0,%1,%2,%3}, [%4];"
        : "=r"(r0), "=r"(r1), "=r"(r2), "=r"(r3) : "r"(addr));
}

#define LDP 20           // u32 pitch per smem row (16 data + 4 pad)
#define KT1 (DIN / 16)   // 57 k-tiles for fc1 (fp32/tf32)
#define KTH (H2 / 32)    // 32 k-tiles for fc2 (fp16)

// ---------------------------------------------------------------------------
// K6: fc2 GEMM fp16 (proven R15: ldmatrix fragments, 128 threads, 2x2 warps,
// warp tile 64x64, m16n8k16, cp.async 2-stage, fused exp+rowsum epilogue).
// ---------------------------------------------------------------------------
__global__ __launch_bounds__(128) void k_fc2(const float* __restrict__ fc2_b) {
    __shared__ unsigned As[2][128][LDP];
    __shared__ unsigned Bs[2][128][LDP];

    int tid = threadIdx.x;
    int bm = blockIdx.y;            // 0..1
    int bn = blockIdx.x;            // 0..390
    int warp = tid >> 5, lane = tid & 31;
    int wm = warp >> 1;
    int wn = warp & 1;
    int nBase = bn * 128;

    float c[4][8][4];
    #pragma unroll
    for (int i = 0; i < 4; i++)
        #pragma unroll
        for (int j = 0; j < 8; j++)
            #pragma unroll
            for (int k = 0; k < 4; k++) c[i][j][k] = 0.f;

    int crow[4], cofH[4], cofU[4];
    #pragma unroll
    for (int p = 0; p < 4; p++) {
        int ch = tid + p * 128;
        crow[p] = ch >> 2;
        cofH[p] = (ch & 3) * 8;
        cofU[p] = (ch & 3) * 4;
    }

    const __half* A = g_fc1h;

    auto issue = [&](int kt, int s) {
        #pragma unroll
        for (int p = 0; p < 4; p++) {
            const __half* a = A + (size_t)(bm * 128 + crow[p]) * H2 + kt * 32 + cofH[p];
            CP_ASYNC((unsigned)__cvta_generic_to_shared(&As[s][crow[p]][cofU[p]]), a);
        }
        #pragma unroll
        for (int p = 0; p < 4; p++) {
            const __half* b = g_wh + (size_t)(nBase + crow[p]) * H2 + kt * 32 + cofH[p];
            CP_ASYNC((unsigned)__cvta_generic_to_shared(&Bs[s][crow[p]][cofU[p]]), b);
        }
        CP_COMMIT();
    };

    int l7  = lane & 7;
    int l8  = (lane >> 3) & 1;
    int l16 = (lane >> 4) & 1;
    int aRow = l7 + l8 * 8;
    int aCol = l16 * 4;
    int bRow = l7 + l16 * 8;
    int bCol = l8 * 4;

    unsigned aBase[2], bBase[2];
    aBase[0] = (unsigned)__cvta_generic_to_shared(&As[0][0][0]);
    aBase[1] = (unsigned)__cvta_generic_to_shared(&As[1][0][0]);
    bBase[0] = (unsigned)__cvta_generic_to_shared(&Bs[0][0][0]);
    bBase[1] = (unsigned)__cvta_generic_to_shared(&Bs[1][0][0]);

    issue(0, 0);

    for (int kt = 0; kt < KTH; kt++) {
        int s = kt & 1;
        if (kt + 1 < KTH) {
            issue(kt + 1, s ^ 1);
            CP_WAIT(1);
        } else {
            CP_WAIT(0);
        }
        __syncthreads();

        #pragma unroll
        for (int ks = 0; ks < 2; ks++) {
            unsigned afr[4][4], bfr[8][2];
            #pragma unroll
            for (int mt = 0; mt < 4; mt++) {
                unsigned ad = aBase[s] +
                    ((unsigned)((wm * 64 + mt * 16 + aRow) * LDP + ks * 8 + aCol) << 2);
                ldsm_x4(afr[mt][0], afr[mt][1], afr[mt][2], afr[mt][3], ad);
            }
            #pragma unroll
            for (int pr = 0; pr < 4; pr++) {
                unsigned bd = bBase[s] +
                    ((unsigned)((wn * 64 + pr * 16 + bRow) * LDP + ks * 8 + bCol) << 2);
                ldsm_x4(bfr[pr * 2][0], bfr[pr * 2][1], bfr[pr * 2 + 1][0], bfr[pr * 2 + 1][1], bd);
            }
            #pragma unroll
            for (int mt = 0; mt < 4; mt++)
                #pragma unroll
                for (int nt = 0; nt < 8; nt++)
                    mma_f16(c[mt][nt], afr[mt], bfr[nt]);
        }
        __syncthreads();
    }

    #pragma unroll
    for (int mt = 0; mt < 4; mt++) {
        int r = bm * 128 + wm * 64 + mt * 16 + (lane >> 2);
        float rs0 = 0.f, rs1 = 0.f;
        #pragma unroll
        for (int nt = 0; nt < 8; nt++) {
            int col = nBase + wn * 64 + nt * 8 + 2 * (lane & 3);
            if (col < Vn) {
                float e0 = expf(c[mt][nt][0] + fc2_b[col]);
                float e2 = expf(c[mt][nt][2] + fc2_b[col]);
                g_exp[(size_t)r * Vn + col]       = e0;
                g_exp[(size_t)(r + 8) * Vn + col] = e2;
                rs0 += e0; rs1 += e2;
            }
            if (col + 1 < Vn) {
                float e1 = expf(c[mt][nt][1] + fc2_b[col + 1]);
                float e3 = expf(c[mt][nt][3] + fc2_b[col + 1]);
                g_exp[(size_t)r * Vn + col + 1]       = e1;
                g_exp[(size_t)(r + 8) * Vn + col + 1] = e3;
                rs0 += e1; rs1 += e3;
            }
        }
        rs0 += __shfl_xor_sync(0xFFFFFFFFu, rs0, 1);
        rs0 += __shfl_xor_sync(0xFFFFFFFFu, rs0, 2);
        rs1 += __shfl_xor_sync(0xFFFFFFFFu, rs1, 1);
        rs1 += __shfl_xor_sync(0xFFFFFFFFu, rs1, 2);
        if ((lane & 3) == 0) {
            atomicAdd(&g_sum[r], rs0);
            atomicAdd(&g_sum[r + 8], rs1);
        }
    }
}

// ---------------------------------------------------------------------------
// K4': fc1 GEMM (256 x 1024 x 912), proven tf32 version; fp16 epilogue.
// ---------------------------------------------------------------------------
__global__ __launch_bounds__(256, 1) void k_fc1g(const float* __restrict__ fc1_w,
                                                 const float* __restrict__ fc1_b) {
    __shared__ float As[2][128][LDP];
    __shared__ float Bs[2][128][LDP];

    int tid = threadIdx.x;
    int bm = blockIdx.y;
    int bn = blockIdx.x;
    int warp = tid >> 5, lane = tid & 31;
    int wm = warp >> 2;
    int wn = warp & 3;
    int nBase = bn * 128;

    float c[4][4][4];
    #pragma unroll
    for (int i = 0; i < 4; i++)
        #pragma unroll
        for (int j = 0; j < 4; j++)
            #pragma unroll
            for (int k = 0; k < 4; k++) c[i][j][k] = 0.f;

    int crow0 = tid >> 2;
    int coff0 = (tid & 3);
    int crow1 = (tid + 256) >> 2;
    int coff1 = ((tid + 256) & 3);

    const float* A = g_din;

    auto issue = [&](int kt, int s) {
        const float* a0 = A + (size_t)(bm * 128 + crow0) * DIN + kt * 16 + coff0 * 4;
        const float* a1 = A + (size_t)(bm * 128 + crow1) * DIN + kt * 16 + coff1 * 4;
        const float* b0 = fc1_w + (size_t)(nBase + crow0) * DIN + kt * 16 + coff0 * 4;
        const float* b1 = fc1_w + (size_t)(nBase + crow1) * DIN + kt * 16 + coff1 * 4;
        CP_ASYNC((unsigned)__cvta_generic_to_shared(&As[s][crow0][coff0 * 4]), a0);
        CP_ASYNC((unsigned)__cvta_generic_to_shared(&As[s][crow1][coff1 * 4]), a1);
        CP_ASYNC((unsigned)__cvta_generic_to_shared(&Bs[s][crow0][coff0 * 4]), b0);
        CP_ASYNC((unsigned)__cvta_generic_to_shared(&Bs[s][crow1][coff1 * 4]), b1);
        CP_COMMIT();
    };

    issue(0, 0);

    for (int kt = 0; kt < KT1; kt++) {
        int s = kt & 1;
        if (kt + 1 < KT1) {
            issue(kt + 1, s ^ 1);
            CP_WAIT(1);
        } else {
            CP_WAIT(0);
        }
        __syncthreads();

        #pragma unroll
        for (int ks = 0; ks < 2; ks++) {
            unsigned afr[4][4], bfr[4][2];
            int k0 = ks * 8 + (lane & 3);
            #pragma unroll
            for (int mt = 0; mt < 4; mt++) {
                int r0 = wm * 64 + mt * 16 + (lane >> 2);
                afr[mt][0] = __float_as_uint(As[s][r0][k0]);
                afr[mt][1] = __float_as_uint(As[s][r0 + 8][k0]);
                afr[mt][2] = __float_as_uint(As[s][r0][k0 + 4]);
                afr[mt][3] = __float_as_uint(As[s][r0 + 8][k0 + 4]);
            }
            #pragma unroll
            for (int nt = 0; nt < 4; nt++) {
                int n0 = wn * 32 + nt * 8 + (lane >> 2);
                bfr[nt][0] = __float_as_uint(Bs[s][n0][k0]);
                bfr[nt][1] = __float_as_uint(Bs[s][n0][k0 + 4]);
            }
            #pragma unroll
            for (int mt = 0; mt < 4; mt++)
                #pragma unroll
                for (int nt = 0; nt < 4; nt++)
                    mma_tf32(c[mt][nt], afr[mt], bfr[nt]);
        }
        __syncthreads();
    }

    #pragma unroll
    for (int mt = 0; mt < 4; mt++) {
        int r = bm * 128 + wm * 64 + mt * 16 + (lane >> 2);
        #pragma unroll
        for (int nt = 0; nt < 4; nt++) {
            int col = nBase + wn * 32 + nt * 8 + 2 * (lane & 3);
            float b0 = fc1_b[col], b1 = fc1_b[col + 1];
            __half2 p0 = __floats2half2_rn(c[mt][nt][0] + b0, c[mt][nt][1] + b1);
            __half2 p1 = __floats2half2_rn(c[mt][nt][2] + b0, c[mt][nt][3] + b1);
            *(__half2*)(g_fc1h + (size_t)r * H2 + col) = p0;
            *(__half2*)(g_fc1h + (size_t)(r + 8) * H2 + col) = p1;
        }
    }
}

// ---------------------------------------------------------------------------
// K8: finalize (proven)
// ---------------------------------------------------------------------------
__global__ void k_final(float* __restrict__ out) {
    int b = blockIdx.y;
    int v = blockIdx.x * blockDim.x + threadIdx.x;
    if (v >= Pn) return;
    float scale = g_gen[b] / g_sum[b];
    float r = 0.f;
    if (v < Vn) r = scale * g_exp[(size_t)b * Vn + v];
    out[(size_t)b * Pn + v] = r;
}

// ---------------------------------------------------------------------------
// K9: scatter-add (proven)
// ---------------------------------------------------------------------------
__global__ void k_scatter(float* __restrict__ out, const int* __restrict__ ids) {
    int b = blockIdx.x;
    int a = threadIdx.x;
    if (a < An) {
        float w = (1.0f - g_gen[b]) * g_att[b * An + a];
        int id = ids[b * An + a];
        atomicAdd(&out[(size_t)b * Pn + id], w);
    }
}

// ---------------------------------------------------------------------------
extern "C" void kernel_launch(void* const* d_in, const int* in_sizes, int n_in,
                              void* d_out, int out_size) {
    const float* x         = (const float*)d_in[0];
    const float* enc_out   = (const float*)d_in[2];
    const float* enc_state = (const float*)d_in[4];
    const int*   ids       = (const int*)d_in[6];
    const float* W_ih      = (const float*)d_in[7];
    const float* b_ih      = (const float*)d_in[9];
    const float* b_hh      = (const float*)d_in[10];
    const float* Wh_w      = (const float*)d_in[11];
    const float* Wh_b      = (const float*)d_in[12];
    const float* Ws_w      = (const float*)d_in[13];
    const float* Ws_b      = (const float*)d_in[14];
    const float* vvec      = (const float*)d_in[15];
    const float* fc1_w     = (const float*)d_in[16];
    const float* fc1_b     = (const float*)d_in[17];
    const float* fc2_w     = (const float*)d_in[18];
    const float* fc2_b     = (const float*)d_in[19];
    const float* pg1       = (const float*)d_in[20];
    const float* pg2       = (const float*)d_in[21];
    const float* pg3       = (const float*)d_in[22];
    float* out = (float*)d_out;

    static cudaStream_t s2 = nullptr;
    static cudaEvent_t evFork = nullptr, evJoin = nullptr;
    if (!s2) {
        cudaStreamCreateWithFlags(&s2, cudaStreamNonBlocking);
        cudaEventCreateWithFlags(&evFork, cudaEventDisableTiming);
        cudaEventCreateWithFlags(&evJoin, cudaEventDisableTiming);
    }

    // fork: run fc2_w conversion concurrently with the front-end chain
    cudaEventRecord(evFork, 0);
    cudaStreamWaitEvent(s2, evFork, 0);
    {
        size_t n4 = (size_t)VP * H2 / 4;
        k_cvt2<<<(unsigned)((n4 + 255) / 256), 256, 0, s2>>>(fc2_w);
    }

    k_lstm<<<dim3(8, 32), 256>>>(x, W_ih, b_ih, b_hh);
    k_attn_e<<<dim3(8, 32), 256>>>(enc_state, Wh_w, Wh_b, Ws_w, Ws_b);
    k_attn_soft<<<Bn, 256>>>(vvec);
    k_ctx<<<dim3(4, Bn), 416>>>(enc_out);
    k_ctxred<<<Bn, 416>>>();
    k_gendin<<<Bn, 256>>>(x, pg1, pg2, pg3);
    k_fc1g<<<dim3(H2 / 128, Bn / 128), 256>>>(fc1_w, fc1_b);

    // join: fc2 needs g_wh
    cudaEventRecord(evJoin, s2);
    cudaStreamWaitEvent(0, evJoin, 0);

    k_fc2<<<dim3(NBN, Bn / 128), 128>>>(fc2_b);
    k_final<<<dim3((Pn + 255) / 256, Bn), 256>>>(out);
    k_scatter<<<Bn, 416>>>(out, ids);
}

// round 17
// speedup vs baseline: 1.1008x; 1.1008x over previous
#include <cuda_runtime.h>
#include <cuda_fp16.h>
#include <math.h>
#include <stdint.h>

// Problem constants
#define Bn   256
#define In   256
#define Hn   512
#define An   400
#define Vn   50000
#define OOVn 50
#define Pn   (Vn + OOVn)      // 50050
#define H2   (2 * Hn)          // 1024
#define DIN  (An + Hn)         // 912 = 57*16
#define NBN  391               // fc2 n-blocks (391*128 = 50048)
#define VP   (NBN * 128)       // 50048 padded rows

// Scratch (static device globals: allocation-free rule)
__device__ float g_h[Bn * Hn];
__device__ float g_e[Bn * An];
__device__ float g_att[Bn * An];
__device__ float g_ctxp[4 * Bn * An];
__device__ float g_ctx[Bn * An];
__device__ float g_din[Bn * DIN];
__device__ __half g_fc1h[Bn * H2];               // fc1 out, fp16 (fc2 A operand)
__device__ __half g_wh[(size_t)VP * H2];         // fc2_w fp16 padded, 102.5 MB
__device__ float g_gen[Bn];
__device__ float g_sum[Bn];
__device__ float g_exp[(size_t)Bn * Vn];         // 51.2 MB

__device__ __forceinline__ float sigmoidf(float x) { return 1.0f / (1.0f + expf(-x)); }

__device__ __forceinline__ float warp_sum(float v) {
    #pragma unroll
    for (int o = 16; o; o >>= 1) v += __shfl_xor_sync(0xFFFFFFFFu, v, o);
    return v;
}

__device__ __forceinline__ float block_sum(float v, float* red) {
    int lane = threadIdx.x & 31, warp = threadIdx.x >> 5;
    v = warp_sum(v);
    if (lane == 0) red[warp] = v;
    __syncthreads();
    int nw = (blockDim.x + 31) >> 5;
    float r = (threadIdx.x < nw) ? red[threadIdx.x] : 0.0f;
    if (warp == 0) r = warp_sum(r);
    if (threadIdx.x == 0) red[0] = r;
    __syncthreads();
    return red[0];
}

__device__ __forceinline__ float block_max(float v, float* red) {
    int lane = threadIdx.x & 31, warp = threadIdx.x >> 5;
    #pragma unroll
    for (int o = 16; o; o >>= 1) v = fmaxf(v, __shfl_xor_sync(0xFFFFFFFFu, v, o));
    if (lane == 0) red[warp] = v;
    __syncthreads();
    int nw = (blockDim.x + 31) >> 5;
    float r = (threadIdx.x < nw) ? red[threadIdx.x] : -INFINITY;
    if (warp == 0) {
        #pragma unroll
        for (int o = 16; o; o >>= 1) r = fmaxf(r, __shfl_xor_sync(0xFFFFFFFFu, r, o));
    }
    if (threadIdx.x == 0) red[0] = r;
    __syncthreads();
    return red[0];
}

// ---------------------------------------------------------------------------
// K0: fc2_w (fp32 [50000][1024]) -> g_wh (fp16 [50048][1024], pad rows = 0)
// ---------------------------------------------------------------------------
__global__ void k_cvt2(const float* __restrict__ w) {
    size_t u = (size_t)blockIdx.x * blockDim.x + threadIdx.x;   // float4 index
    size_t row = u >> 8;
    int pos = (int)(u & 255) * 4;
    if (row >= VP) return;
    float4 v = make_float4(0.f, 0.f, 0.f, 0.f);
    if (row < Vn) v = *(const float4*)(w + row * H2 + pos);
    __half2 p0 = __floats2half2_rn(v.x, v.y);
    __half2 p1 = __floats2half2_rn(v.z, v.w);
    uint2 o;
    o.x = *(unsigned*)&p0;
    o.y = *(unsigned*)&p1;
    *(uint2*)(g_wh + row * H2 + pos) = o;
}

// ---------------------------------------------------------------------------
// K1: LSTM cell — proven R11 version (grid 8x32)
// ---------------------------------------------------------------------------
__global__ __launch_bounds__(256) void k_lstm(const float* __restrict__ x,
                                              const float* __restrict__ W_ih,
                                              const float* __restrict__ b_ih,
                                              const float* __restrict__ b_hh) {
    int jc = blockIdx.x;
    int b0 = blockIdx.y * 8;
    __shared__ float sx[8][In];
    for (int idx = threadIdx.x; idx < 8 * In; idx += blockDim.x) {
        int bb = idx >> 8, k = idx & 255;
        sx[bb][k] = x[(b0 + bb) * In + k];
    }
    __syncthreads();
    int warp = threadIdx.x >> 5, lane = threadIdx.x & 31;
    for (int jj = 0; jj < 8; jj++) {
        int j = jc * 64 + jj * 8 + warp;
        const float* wi = W_ih + (size_t)j * In;
        const float* wg = W_ih + (size_t)(2 * Hn + j) * In;
        const float* wo = W_ih + (size_t)(3 * Hn + j) * In;
        float wiR[8], wgR[8], woR[8];
        #pragma unroll
        for (int p = 0; p < 8; p++) {
            int k = lane + 32 * p;
            wiR[p] = wi[k]; wgR[p] = wg[k]; woR[p] = wo[k];
        }
        float bi = b_ih[j] + b_hh[j];
        float bg = b_ih[2 * Hn + j] + b_hh[2 * Hn + j];
        float bo = b_ih[3 * Hn + j] + b_hh[3 * Hn + j];
        #pragma unroll
        for (int bb = 0; bb < 8; bb++) {
            float ai = 0.f, ag = 0.f, ao = 0.f;
            #pragma unroll
            for (int p = 0; p < 8; p++) {
                float xv = sx[bb][lane + 32 * p];
                ai = fmaf(xv, wiR[p], ai);
                ag = fmaf(xv, wgR[p], ag);
                ao = fmaf(xv, woR[p], ao);
            }
            ai = warp_sum(ai); ag = warp_sum(ag); ao = warp_sum(ao);
            if (lane == 0) {
                float ai2 = ai + bi, ag2 = ag + bg, ao2 = ao + bo;
                float c = sigmoidf(ai2) * tanhf(ag2);
                g_h[(b0 + bb) * Hn + j] = sigmoidf(ao2) * tanhf(c);
            }
        }
    }
}

// ---------------------------------------------------------------------------
// K2a/K2b: attention (proven R11)
// ---------------------------------------------------------------------------
__global__ __launch_bounds__(256) void k_attn_e(const float* __restrict__ enc_state,
                                                const float* __restrict__ Wh_w,
                                                const float* __restrict__ Wh_b,
                                                const float* __restrict__ Ws_w,
                                                const float* __restrict__ Ws_b) {
    int ac = blockIdx.x;
    int b0 = blockIdx.y * 8;
    __shared__ float ss[8][Hn];
    __shared__ float sh[8][Hn];
    for (int idx = threadIdx.x; idx < 8 * Hn; idx += blockDim.x) {
        int bb = idx >> 9, k = idx & 511;
        ss[bb][k] = enc_state[(b0 + bb) * Hn + k];
        sh[bb][k] = g_h[(b0 + bb) * Hn + k];
    }
    __syncthreads();
    int warp = threadIdx.x >> 5, lane = threadIdx.x & 31;
    for (int aa = warp; aa < 50; aa += 8) {
        int a = ac * 50 + aa;
        const float* w1 = Wh_w + (size_t)a * Hn;
        const float* w2 = Ws_w + (size_t)a * Hn;
        float w1R[16], w2R[16];
        #pragma unroll
        for (int p = 0; p < 16; p++) {
            int k = lane + 32 * p;
            w1R[p] = w1[k]; w2R[p] = w2[k];
        }
        float bias = Wh_b[a] + Ws_b[a];
        #pragma unroll
        for (int bb = 0; bb < 8; bb++) {
            float acc = 0.f;
            #pragma unroll
            for (int p = 0; p < 16; p++) {
                int k = lane + 32 * p;
                acc = fmaf(ss[bb][k], w1R[p], fmaf(sh[bb][k], w2R[p], acc));
            }
            acc = warp_sum(acc);
            if (lane == 0) g_e[(b0 + bb) * An + a] = tanhf(acc + bias);
        }
    }
}

__global__ __launch_bounds__(256) void k_attn_soft(const float* __restrict__ vvec) {
    int b = blockIdx.x;
    __shared__ float red[32];
    float m = -INFINITY;
    for (int i = threadIdx.x; i < An; i += blockDim.x) m = fmaxf(m, g_e[b * An + i]);
    m = block_max(m, red);
    float s = 0.f;
    for (int i = threadIdx.x; i < An; i += blockDim.x) s += expf(g_e[b * An + i] - m);
    s = block_sum(s, red);
    float inv = 1.0f / s;
    for (int i = threadIdx.x; i < An; i += blockDim.x)
        g_att[b * An + i] = vvec[i] * expf(g_e[b * An + i] - m) * inv;
}

// ---------------------------------------------------------------------------
// K3: context partials — float4 loads, per-element accumulation order
// identical to the proven scalar version (i ascending) -> bit-identical.
// ---------------------------------------------------------------------------
__global__ void k_ctx(const float* __restrict__ enc_out) {
    int slice = blockIdx.x;     // 0..3
    int b = blockIdx.y;
    int a0 = slice * 100;
    __shared__ float sa[100];
    if (threadIdx.x < 100) sa[threadIdx.x] = g_att[b * An + a0 + threadIdx.x];
    __syncthreads();
    int e4 = threadIdx.x;       // 0..99 (blockDim 128)
    if (e4 < 100) {
        const float4* base = (const float4*)(enc_out + ((size_t)b * An + a0) * An) + e4;
        float4 acc = make_float4(0.f, 0.f, 0.f, 0.f);
        #pragma unroll 4
        for (int i = 0; i < 100; i++) {
            float4 v = base[(size_t)i * 100];
            float w = sa[i];
            acc.x = fmaf(w, v.x, acc.x);
            acc.y = fmaf(w, v.y, acc.y);
            acc.z = fmaf(w, v.z, acc.z);
            acc.w = fmaf(w, v.w, acc.w);
        }
        ((float4*)(g_ctxp + ((size_t)slice * Bn + b) * An))[e4] = acc;
    }
}

__global__ void k_ctxred() {
    int b = blockIdx.x;
    int e4 = threadIdx.x;       // 0..99 (blockDim 128)
    if (e4 < 100) {
        float4 s0 = ((const float4*)(g_ctxp + ((size_t)0 * Bn + b) * An))[e4];
        float4 s1 = ((const float4*)(g_ctxp + ((size_t)1 * Bn + b) * An))[e4];
        float4 s2 = ((const float4*)(g_ctxp + ((size_t)2 * Bn + b) * An))[e4];
        float4 s3 = ((const float4*)(g_ctxp + ((size_t)3 * Bn + b) * An))[e4];
        float4 r;
        r.x = s0.x + s1.x + s2.x + s3.x;
        r.y = s0.y + s1.y + s2.y + s3.y;
        r.z = s0.z + s1.z + s2.z + s3.z;
        r.w = s0.w + s1.w + s2.w + s3.w;
        ((float4*)(g_ctx + (size_t)b * An))[e4] = r;
    }
}

// ---------------------------------------------------------------------------
// K5: gen gate + dec_in + g_sum zero (proven R11)
// ---------------------------------------------------------------------------
__global__ void k_gendin(const float* __restrict__ x, const float* __restrict__ pg1,
                         const float* __restrict__ pg2, const float* __restrict__ pg3) {
    int b = blockIdx.x;
    __shared__ float red[32];
    float acc = 0.f;
    for (int k = threadIdx.x; k < In; k += blockDim.x) acc = fmaf(x[b * In + k], pg1[k], acc);
    for (int k = threadIdx.x; k < An; k += blockDim.x) acc = fmaf(g_ctx[b * An + k], pg2[k], acc);
    for (int k = threadIdx.x; k < Hn; k += blockDim.x) acc = fmaf(g_h[b * Hn + k], pg3[k], acc);
    acc = block_sum(acc, red);
    if (threadIdx.x == 0) {
        g_gen[b] = sigmoidf(acc);
        g_sum[b] = 0.0f;
    }
    for (int i = threadIdx.x; i < DIN; i += blockDim.x) {
        float v = (i < An) ? g_ctx[b * An + i] : g_h[b * Hn + (i - An)];
        g_din[b * DIN + i] = v;
    }
}

// ---------------------------------------------------------------------------
// GEMM machinery
// ---------------------------------------------------------------------------
#define CP_ASYNC(dst, src)        asm volatile("cp.async.cg.shared.global [%0], [%1], 16;" :: "r"(dst), "l"(src))
#define CP_COMMIT()               asm volatile("cp.async.commit_group;")
#define CP_WAIT(n)                asm volatile("cp.async.wait_group %0;" :: "n"(n))

__device__ __forceinline__ void mma_tf32(float c[4], const unsigned a[4], const unsigned b[2]) {
    asm volatile(
        "mma.sync.aligned.m16n8k8.row.col.f32.tf32.tf32.f32 "
        "{%0,%1,%2,%3}, {%4,%5,%6,%7}, {%8,%9}, {%0,%1,%2,%3};"
        : "+f"(c[0]), "+f"(c[1]), "+f"(c[2]), "+f"(c[3])
        : "r"(a[0]), "r"(a[1]), "r"(a[2]), "r"(a[3]), "r"(b[0]), "r"(b[1]));
}

__device__ __forceinline__ void mma_f16(float c[4], const unsigned a[4], const unsigned b[2]) {
    asm volatile(
        "mma.sync.aligned.m16n8k16.row.col.f32.f16.f16.f32 "
        "{%0,%1,%2,%3}, {%4,%5,%6,%7}, {%8,%9}, {%0,%1,%2,%3};"
        : "+f"(c[0]), "+f"(c[1]), "+f"(c[2]), "+f"(c[3])
        : "r"(a[0]), "r"(a[1]), "r"(a[2]), "r"(a[3]), "r"(b[0]), "r"(b[1]));
}

__device__ __forceinline__ void ldsm_x4(unsigned& r0, unsigned& r1, unsigned& r2, unsigned& r3,
                                        unsigned addr) {
    asm volatile("ldmatrix.sync.aligned.m8n8.x4.shared.b16 {%0,%1,%2,%3}, [%4];"
        : "=r"(r0), "=r"(r1), "=r"(r2), "=r"(r3) : "r"(addr));
}

#define LDP 20           // u32 pitch per smem row (16 data + 4 pad)
#define KT1 (DIN / 16)   // 57 k-tiles for fc1 (fp32/tf32)
#define KTH (H2 / 32)    // 32 k-tiles for fc2 (fp16)

// ---------------------------------------------------------------------------
// K6: fc2 GEMM fp16 (proven R15: ldmatrix fragments, 128 threads, 2x2 warps,
// warp tile 64x64, m16n8k16, cp.async 2-stage, fused exp+rowsum epilogue).
// ---------------------------------------------------------------------------
__global__ __launch_bounds__(128) void k_fc2(const float* __restrict__ fc2_b) {
    __shared__ unsigned As[2][128][LDP];
    __shared__ unsigned Bs[2][128][LDP];

    int tid = threadIdx.x;
    int bm = blockIdx.y;            // 0..1
    int bn = blockIdx.x;            // 0..390
    int warp = tid >> 5, lane = tid & 31;
    int wm = warp >> 1;
    int wn = warp & 1;
    int nBase = bn * 128;

    float c[4][8][4];
    #pragma unroll
    for (int i = 0; i < 4; i++)
        #pragma unroll
        for (int j = 0; j < 8; j++)
            #pragma unroll
            for (int k = 0; k < 4; k++) c[i][j][k] = 0.f;

    int crow[4], cofH[4], cofU[4];
    #pragma unroll
    for (int p = 0; p < 4; p++) {
        int ch = tid + p * 128;
        crow[p] = ch >> 2;
        cofH[p] = (ch & 3) * 8;
        cofU[p] = (ch & 3) * 4;
    }

    const __half* A = g_fc1h;

    auto issue = [&](int kt, int s) {
        #pragma unroll
        for (int p = 0; p < 4; p++) {
            const __half* a = A + (size_t)(bm * 128 + crow[p]) * H2 + kt * 32 + cofH[p];
            CP_ASYNC((unsigned)__cvta_generic_to_shared(&As[s][crow[p]][cofU[p]]), a);
        }
        #pragma unroll
        for (int p = 0; p < 4; p++) {
            const __half* b = g_wh + (size_t)(nBase + crow[p]) * H2 + kt * 32 + cofH[p];
            CP_ASYNC((unsigned)__cvta_generic_to_shared(&Bs[s][crow[p]][cofU[p]]), b);
        }
        CP_COMMIT();
    };

    int l7  = lane & 7;
    int l8  = (lane >> 3) & 1;
    int l16 = (lane >> 4) & 1;
    int aRow = l7 + l8 * 8;
    int aCol = l16 * 4;
    int bRow = l7 + l16 * 8;
    int bCol = l8 * 4;

    unsigned aBase[2], bBase[2];
    aBase[0] = (unsigned)__cvta_generic_to_shared(&As[0][0][0]);
    aBase[1] = (unsigned)__cvta_generic_to_shared(&As[1][0][0]);
    bBase[0] = (unsigned)__cvta_generic_to_shared(&Bs[0][0][0]);
    bBase[1] = (unsigned)__cvta_generic_to_shared(&Bs[1][0][0]);

    issue(0, 0);

    for (int kt = 0; kt < KTH; kt++) {
        int s = kt & 1;
        if (kt + 1 < KTH) {
            issue(kt + 1, s ^ 1);
            CP_WAIT(1);
        } else {
            CP_WAIT(0);
        }
        __syncthreads();

        #pragma unroll
        for (int ks = 0; ks < 2; ks++) {
            unsigned afr[4][4], bfr[8][2];
            #pragma unroll
            for (int mt = 0; mt < 4; mt++) {
                unsigned ad = aBase[s] +
                    ((unsigned)((wm * 64 + mt * 16 + aRow) * LDP + ks * 8 + aCol) << 2);
                ldsm_x4(afr[mt][0], afr[mt][1], afr[mt][2], afr[mt][3], ad);
            }
            #pragma unroll
            for (int pr = 0; pr < 4; pr++) {
                unsigned bd = bBase[s] +
                    ((unsigned)((wn * 64 + pr * 16 + bRow) * LDP + ks * 8 + bCol) << 2);
                ldsm_x4(bfr[pr * 2][0], bfr[pr * 2][1], bfr[pr * 2 + 1][0], bfr[pr * 2 + 1][1], bd);
            }
            #pragma unroll
            for (int mt = 0; mt < 4; mt++)
                #pragma unroll
                for (int nt = 0; nt < 8; nt++)
                    mma_f16(c[mt][nt], afr[mt], bfr[nt]);
        }
        __syncthreads();
    }

    #pragma unroll
    for (int mt = 0; mt < 4; mt++) {
        int r = bm * 128 + wm * 64 + mt * 16 + (lane >> 2);
        float rs0 = 0.f, rs1 = 0.f;
        #pragma unroll
        for (int nt = 0; nt < 8; nt++) {
            int col = nBase + wn * 64 + nt * 8 + 2 * (lane & 3);
            if (col < Vn) {
                float e0 = expf(c[mt][nt][0] + fc2_b[col]);
                float e2 = expf(c[mt][nt][2] + fc2_b[col]);
                g_exp[(size_t)r * Vn + col]       = e0;
                g_exp[(size_t)(r + 8) * Vn + col] = e2;
                rs0 += e0; rs1 += e2;
            }
            if (col + 1 < Vn) {
                float e1 = expf(c[mt][nt][1] + fc2_b[col + 1]);
                float e3 = expf(c[mt][nt][3] + fc2_b[col + 1]);
                g_exp[(size_t)r * Vn + col + 1]       = e1;
                g_exp[(size_t)(r + 8) * Vn + col + 1] = e3;
                rs0 += e1; rs1 += e3;
            }
        }
        rs0 += __shfl_xor_sync(0xFFFFFFFFu, rs0, 1);
        rs0 += __shfl_xor_sync(0xFFFFFFFFu, rs0, 2);
        rs1 += __shfl_xor_sync(0xFFFFFFFFu, rs1, 1);
        rs1 += __shfl_xor_sync(0xFFFFFFFFu, rs1, 2);
        if ((lane & 3) == 0) {
            atomicAdd(&g_sum[r], rs0);
            atomicAdd(&g_sum[r + 8], rs1);
        }
    }
}

// ---------------------------------------------------------------------------
// K4': fc1 GEMM (256 x 1024 x 912), proven tf32 version; fp16 epilogue.
// ---------------------------------------------------------------------------
__global__ __launch_bounds__(256, 1) void k_fc1g(const float* __restrict__ fc1_w,
                                                 const float* __restrict__ fc1_b) {
    __shared__ float As[2][128][LDP];
    __shared__ float Bs[2][128][LDP];

    int tid = threadIdx.x;
    int bm = blockIdx.y;
    int bn = blockIdx.x;
    int warp = tid >> 5, lane = tid & 31;
    int wm = warp >> 2;
    int wn = warp & 3;
    int nBase = bn * 128;

    float c[4][4][4];
    #pragma unroll
    for (int i = 0; i < 4; i++)
        #pragma unroll
        for (int j = 0; j < 4; j++)
            #pragma unroll
            for (int k = 0; k < 4; k++) c[i][j][k] = 0.f;

    int crow0 = tid >> 2;
    int coff0 = (tid & 3);
    int crow1 = (tid + 256) >> 2;
    int coff1 = ((tid + 256) & 3);

    const float* A = g_din;

    auto issue = [&](int kt, int s) {
        const float* a0 = A + (size_t)(bm * 128 + crow0) * DIN + kt * 16 + coff0 * 4;
        const float* a1 = A + (size_t)(bm * 128 + crow1) * DIN + kt * 16 + coff1 * 4;
        const float* b0 = fc1_w + (size_t)(nBase + crow0) * DIN + kt * 16 + coff0 * 4;
        const float* b1 = fc1_w + (size_t)(nBase + crow1) * DIN + kt * 16 + coff1 * 4;
        CP_ASYNC((unsigned)__cvta_generic_to_shared(&As[s][crow0][coff0 * 4]), a0);
        CP_ASYNC((unsigned)__cvta_generic_to_shared(&As[s][crow1][coff1 * 4]), a1);
        CP_ASYNC((unsigned)__cvta_generic_to_shared(&Bs[s][crow0][coff0 * 4]), b0);
        CP_ASYNC((unsigned)__cvta_generic_to_shared(&Bs[s][crow1][coff1 * 4]), b1);
        CP_COMMIT();
    };

    issue(0, 0);

    for (int kt = 0; kt < KT1; kt++) {
        int s = kt & 1;
        if (kt + 1 < KT1) {
            issue(kt + 1, s ^ 1);
            CP_WAIT(1);
        } else {
            CP_WAIT(0);
        }
        __syncthreads();

        #pragma unroll
        for (int ks = 0; ks < 2; ks++) {
            unsigned afr[4][4], bfr[4][2];
            int k0 = ks * 8 + (lane & 3);
            #pragma unroll
            for (int mt = 0; mt < 4; mt++) {
                int r0 = wm * 64 + mt * 16 + (lane >> 2);
                afr[mt][0] = __float_as_uint(As[s][r0][k0]);
                afr[mt][1] = __float_as_uint(As[s][r0 + 8][k0]);
                afr[mt][2] = __float_as_uint(As[s][r0][k0 + 4]);
                afr[mt][3] = __float_as_uint(As[s][r0 + 8][k0 + 4]);
            }
            #pragma unroll
            for (int nt = 0; nt < 4; nt++) {
                int n0 = wn * 32 + nt * 8 + (lane >> 2);
                bfr[nt][0] = __float_as_uint(Bs[s][n0][k0]);
                bfr[nt][1] = __float_as_uint(Bs[s][n0][k0 + 4]);
            }
            #pragma unroll
            for (int mt = 0; mt < 4; mt++)
                #pragma unroll
                for (int nt = 0; nt < 4; nt++)
                    mma_tf32(c[mt][nt], afr[mt], bfr[nt]);
        }
        __syncthreads();
    }

    #pragma unroll
    for (int mt = 0; mt < 4; mt++) {
        int r = bm * 128 + wm * 64 + mt * 16 + (lane >> 2);
        #pragma unroll
        for (int nt = 0; nt < 4; nt++) {
            int col = nBase + wn * 32 + nt * 8 + 2 * (lane & 3);
            float b0 = fc1_b[col], b1 = fc1_b[col + 1];
            __half2 p0 = __floats2half2_rn(c[mt][nt][0] + b0, c[mt][nt][1] + b1);
            __half2 p1 = __floats2half2_rn(c[mt][nt][2] + b0, c[mt][nt][3] + b1);
            *(__half2*)(g_fc1h + (size_t)r * H2 + col) = p0;
            *(__half2*)(g_fc1h + (size_t)(r + 8) * H2 + col) = p1;
        }
    }
}

// ---------------------------------------------------------------------------
// K8: finalize (proven)
// ---------------------------------------------------------------------------
__global__ void k_final(float* __restrict__ out) {
    int b = blockIdx.y;
    int v = blockIdx.x * blockDim.x + threadIdx.x;
    if (v >= Pn) return;
    float scale = g_gen[b] / g_sum[b];
    float r = 0.f;
    if (v < Vn) r = scale * g_exp[(size_t)b * Vn + v];
    out[(size_t)b * Pn + v] = r;
}

// ---------------------------------------------------------------------------
// K9: scatter-add (proven)
// ---------------------------------------------------------------------------
__global__ void k_scatter(float* __restrict__ out, const int* __restrict__ ids) {
    int b = blockIdx.x;
    int a = threadIdx.x;
    if (a < An) {
        float w = (1.0f - g_gen[b]) * g_att[b * An + a];
        int id = ids[b * An + a];
        atomicAdd(&out[(size_t)b * Pn + id], w);
    }
}

// ---------------------------------------------------------------------------
extern "C" void kernel_launch(void* const* d_in, const int* in_sizes, int n_in,
                              void* d_out, int out_size) {
    const float* x         = (const float*)d_in[0];
    const float* enc_out   = (const float*)d_in[2];
    const float* enc_state = (const float*)d_in[4];
    const int*   ids       = (const int*)d_in[6];
    const float* W_ih      = (const float*)d_in[7];
    const float* b_ih      = (const float*)d_in[9];
    const float* b_hh      = (const float*)d_in[10];
    const float* Wh_w      = (const float*)d_in[11];
    const float* Wh_b      = (const float*)d_in[12];
    const float* Ws_w      = (const float*)d_in[13];
    const float* Ws_b      = (const float*)d_in[14];
    const float* vvec      = (const float*)d_in[15];
    const float* fc1_w     = (const float*)d_in[16];
    const float* fc1_b     = (const float*)d_in[17];
    const float* fc2_w     = (const float*)d_in[18];
    const float* fc2_b     = (const float*)d_in[19];
    const float* pg1       = (const float*)d_in[20];
    const float* pg2       = (const float*)d_in[21];
    const float* pg3       = (const float*)d_in[22];
    float* out = (float*)d_out;

    // weight conversion first (serial — overlap with DRAM-bound front-end regresses)
    {
        size_t n4 = (size_t)VP * H2 / 4;
        k_cvt2<<<(unsigned)((n4 + 255) / 256), 256>>>(fc2_w);
    }
    k_lstm<<<dim3(8, 32), 256>>>(x, W_ih, b_ih, b_hh);
    k_attn_e<<<dim3(8, 32), 256>>>(enc_state, Wh_w, Wh_b, Ws_w, Ws_b);
    k_attn_soft<<<Bn, 256>>>(vvec);
    k_ctx<<<dim3(4, Bn), 128>>>(enc_out);
    k_ctxred<<<Bn, 128>>>();
    k_gendin<<<Bn, 256>>>(x, pg1, pg2, pg3);
    k_fc1g<<<dim3(H2 / 128, Bn / 128), 256>>>(fc1_w, fc1_b);
    k_fc2<<<dim3(NBN, Bn / 128), 128>>>(fc2_b);
    k_final<<<dim3((Pn + 255) / 256, Bn), 256>>>(out);
    k_scatter<<<Bn, 416>>>(out, ids);
}